// round 17
// baseline (speedup 1.0000x reference)
#include <cuda_runtime.h>
#include <math.h>
#include <stdint.h>

// ---------------------------------------------------------------------------
// MSDeformableAttention — GB300 (plain sm_103 target: tcgen05 unavailable,
// legacy mma.sync tf32 tensor path, ldmatrix fragment loads, cp.async)
//
//   0) round_prep: query + all weights -> tf32-rounded scratch copies
//   1) tf32_gemm<BK16>: v    = value @ vp_wR + vp_b        (A cvt in-loop)
//   2) tf32_gemm<BK32>: soaw = queryR @ [so_wR|aw_wR] + bias
//   3) sample: in-warp softmax + bilinear gather (stores tf32-rounded ACC)
//   4) tf32_gemm<BK32>: out  = ACC @ op_wR + op_b
//
// Pre-rounded operands make the in-loop cvt.rna redundant (mma's tf32
// truncation of an rna-rounded fp32 is the identity) — bit-identical
// results with far fewer issues per stage.
//
// B=8, LQ=1024, LV=13294, D=256, H=8, HD=32, L=4, P=4
// levels (h=w,start): (100,0) (50,10000) (25,12500) (13,13125)
// ---------------------------------------------------------------------------

namespace cfg {
constexpr int B  = 8;
constexpr int LQ = 1024;
constexpr int LV = 13294;
constexpr int D  = 256;
constexpr int H  = 8;

constexpr size_t SZ_V    = (size_t)B * LV * D;      // 27,226,112
constexpr size_t SZ_SOAW = (size_t)B * LQ * 384;
constexpr size_t SZ_ACC  = (size_t)B * LQ * D;
// rounded copies: query(2097152) so_w(65536) aw_w(32768) op_w(65536) vp_w(65536)
constexpr size_t SZ_RND  = 2097152 + 65536 + 32768 + 65536 + 65536; // 2,326,528

constexpr size_t OFF_V    = 0;
constexpr size_t OFF_SOAW = OFF_V    + SZ_V;
constexpr size_t OFF_ACC  = OFF_SOAW + SZ_SOAW;
constexpr size_t OFF_RND  = OFF_ACC  + SZ_ACC;
constexpr size_t SZ_TOT   = OFF_RND  + SZ_RND;      // ~34.8M floats (~139 MB)
}  // namespace cfg

__device__ float g_scratch[cfg::SZ_TOT];

// ---------------------------------------------------------------------------
__device__ __forceinline__ uint32_t f2tf32(float x) {
    uint32_t u;
    asm("cvt.rna.tf32.f32 %0, %1;" : "=r"(u) : "f"(x));
    return u;
}
__device__ __forceinline__ uint32_t frag_tf32(uint32_t bits) {
    return f2tf32(__uint_as_float(bits));
}

__device__ __forceinline__ void mma_tf32(float d[4], const uint32_t a[4],
                                         const uint32_t b[2]) {
    asm volatile(
        "mma.sync.aligned.m16n8k8.row.col.f32.tf32.tf32.f32 "
        "{%0,%1,%2,%3}, {%4,%5,%6,%7}, {%8,%9}, {%0,%1,%2,%3};"
        : "+f"(d[0]), "+f"(d[1]), "+f"(d[2]), "+f"(d[3])
        : "r"(a[0]), "r"(a[1]), "r"(a[2]), "r"(a[3]), "r"(b[0]), "r"(b[1]));
}

__device__ __forceinline__ void ldsm_x4(uint32_t& r0, uint32_t& r1,
                                        uint32_t& r2, uint32_t& r3,
                                        uint32_t saddr) {
    asm volatile(
        "ldmatrix.sync.aligned.m8n8.x4.shared.b16 {%0,%1,%2,%3}, [%4];"
        : "=r"(r0), "=r"(r1), "=r"(r2), "=r"(r3) : "r"(saddr));
}

__device__ __forceinline__ void cpa16(uint32_t dst, const void* src,
                                      int src_bytes) {
    asm volatile("cp.async.cg.shared.global [%0], [%1], 16, %2;"
                 :: "r"(dst), "l"(src), "r"(src_bytes));
}
__device__ __forceinline__ void cpa4(uint32_t dst, const void* src) {
    asm volatile("cp.async.ca.shared.global [%0], [%1], 4;"
                 :: "r"(dst), "l"(src));
}
__device__ __forceinline__ void cpa_commit() {
    asm volatile("cp.async.commit_group;");
}
template <int N>
__device__ __forceinline__ void cpa_wait() {
    asm volatile("cp.async.wait_group %0;" :: "n"(N));
}

// ---------------------------------------------------------------------------
// Pre-round query + weights to tf32 (rna). One launch, segmented ranges.
// float4 counts: q 524288 | so 16384 | aw 8192 | op 16384 | vp 16384
// total 581,632 = 2272 blocks x 256 threads exactly.
// ---------------------------------------------------------------------------
__global__ void round_prep(const float4* __restrict__ q,
                           const float4* __restrict__ so,
                           const float4* __restrict__ aw,
                           const float4* __restrict__ op,
                           const float4* __restrict__ vp,
                           float4* __restrict__ out)
{
    const int i = blockIdx.x * 256 + threadIdx.x;
    const float4* src;
    int j;
    if (i < 524288)      { src = q;  j = i; }
    else if (i < 540672) { src = so; j = i - 524288; }
    else if (i < 548864) { src = aw; j = i - 540672; }
    else if (i < 565248) { src = op; j = i - 548864; }
    else                 { src = vp; j = i - 565248; }
    float4 v = src[j];
    v.x = __uint_as_float(f2tf32(v.x));
    v.y = __uint_as_float(f2tf32(v.y));
    v.z = __uint_as_float(f2tf32(v.z));
    v.w = __uint_as_float(f2tf32(v.w));
    out[i] = v;
}

// ---------------------------------------------------------------------------
// tf32 mma.sync GEMM with bias, dual B source, templated:
//   CVT_A : apply cvt.rna to A fragments in-loop (A not pre-rounded)
//   PLANES: k16-planes per pipeline stage (1 -> BK16, 2 -> BK32)
//   NSLOT : pipeline slots (4 for BK16 [wait2], 3 for BK32 [wait1])
// B operands must be pre-rounded to tf32. Per-plane layout/swizzle is the
// proven R12 scheme. C[M,N] = A[M,K] @ B[K,N] + bias[N]; cols [0,N0) from
// (B0,ldB0,bias0), rest from (B1,ldB1,bias1), per-CTA uniform (N0%128==0).
// Requires K % (16*PLANES) == 0, N % 128 == 0; M guarded.
// ---------------------------------------------------------------------------
template <bool CVT_A, int PLANES, int NSLOT>
__global__ __launch_bounds__(256, (PLANES == 1 ? 2 : 1)) void tf32_gemm_dual(
    const float* __restrict__ A,
    const float* __restrict__ B0, int ldB0,
    const float* __restrict__ B1, int ldB1, int N0,
    const float* __restrict__ bias0, const float* __restrict__ bias1,
    float* __restrict__ C, int M, int N, int K)
{
    __shared__ uint32_t As[NSLOT][PLANES][128 * 16];
    __shared__ uint32_t Bs[NSLOT][PLANES][128 * 16];

    const int tid  = threadIdx.x;
    const int wid  = tid >> 5;
    const int lane = tid & 31;
    const int row0 = blockIdx.y * 128;
    const int col0 = blockIdx.x * 128;
    const int wm   = (wid >> 2) * 64;
    const int wn   = (wid & 3) * 32;

    const bool sel = (col0 >= N0);
    const float* Bbase = sel ? (B1 + (col0 - N0)) : (B0 + col0);
    const int    ldB   = sel ? ldB1 : ldB0;
    const float* biasp = sel ? (bias1 + (col0 - N0)) : (bias0 + col0);

    float acc[4][4][4];
#pragma unroll
    for (int mt = 0; mt < 4; mt++)
#pragma unroll
        for (int nt = 0; nt < 4; nt++)
#pragma unroll
            for (int r = 0; r < 4; r++) acc[mt][nt][r] = 0.0f;

    const int ar = tid >> 1;
    const int ak = (tid & 1) * 8;
    const bool aok = (row0 + ar) < M;
    const int a_srcb = aok ? 16 : 0;
    const float* Ap = A + (size_t)(aok ? (row0 + ar) : 0) * K + ak;
    const int bn  = tid & 127;
    const int bkh = (tid >> 7) * 8;

    const int a_sw  = (ar >> 1) & 3;
    const int a_c0  = ak >> 2;
    const uint32_t a_off0 = ar * 16 + ((a_c0 ^ a_sw) << 2);
    const uint32_t a_off1 = ar * 16 + (((a_c0 + 1) ^ a_sw) << 2);
    const int b_sw  = (bn >> 1) & 3;
    const int b_c0  = bkh >> 2;
    const uint32_t b_off0 = bn * 16 + ((b_c0 ^ b_sw) << 2);
    const uint32_t b_off1 = bn * 16 + (((b_c0 + 1) ^ b_sw) << 2);

    const uint32_t asBase = (uint32_t)__cvta_generic_to_shared(As);
    const uint32_t bsBase = (uint32_t)__cvta_generic_to_shared(Bs);

    int a_mrow[4], a_msw[4];
#pragma unroll
    for (int mt = 0; mt < 4; mt++) {
        a_mrow[mt] = wm + mt * 16 + (lane & 7) + ((lane >> 3) & 1) * 8;
        a_msw[mt]  = (a_mrow[mt] >> 1) & 3;
    }
    const int a_cadd = lane >> 4;
    int b_nrow[2], b_nsw[2];
#pragma unroll
    for (int p = 0; p < 2; p++) {
        b_nrow[p] = wn + p * 16 + (lane & 7) + ((lane >> 4) & 1) * 8;
        b_nsw[p]  = (b_nrow[p] >> 1) & 3;
    }
    const int b_cadd = (lane >> 3) & 1;

    auto issue_copy = [&](int slot, int kbase) {
#pragma unroll
        for (int pl = 0; pl < PLANES; pl++) {
            const int kb = kbase + pl * 16;
            const uint32_t aslot =
                asBase + (uint32_t)(slot * PLANES + pl) * 8192u;
            const uint32_t bslot =
                bsBase + (uint32_t)(slot * PLANES + pl) * 8192u;
            cpa16(aslot + a_off0 * 4u, Ap + kb, a_srcb);
            cpa16(aslot + a_off1 * 4u, Ap + kb + 4, a_srcb);
            const float* bp = Bbase + (size_t)(kb + bkh) * ldB + bn;
#pragma unroll
            for (int i = 0; i < 4; i++)
                cpa4(bslot + (b_off0 + i) * 4u, bp + (size_t)i * ldB);
#pragma unroll
            for (int i = 0; i < 4; i++)
                cpa4(bslot + (b_off1 + i) * 4u, bp + (size_t)(i + 4) * ldB);
        }
    };

    auto compute = [&](int slot) {
#pragma unroll
        for (int pl = 0; pl < PLANES; pl++) {
            const uint32_t aslot =
                asBase + (uint32_t)(slot * PLANES + pl) * 8192u;
            const uint32_t bslot =
                bsBase + (uint32_t)(slot * PLANES + pl) * 8192u;
#pragma unroll
            for (int ks = 0; ks < 2; ks++) {
                const int cb = ks * 2;
                uint32_t bfr[4][2];
#pragma unroll
                for (int p = 0; p < 2; p++) {
                    uint32_t w = (uint32_t)(b_nrow[p] * 16 +
                                            (((cb + b_cadd) ^ b_nsw[p]) << 2));
                    uint32_t r0, r1, r2, r3;
                    ldsm_x4(r0, r1, r2, r3, bslot + w * 4u);
                    bfr[p * 2][0]     = r0;
                    bfr[p * 2][1]     = r1;
                    bfr[p * 2 + 1][0] = r2;
                    bfr[p * 2 + 1][1] = r3;
                }
#pragma unroll
                for (int mt = 0; mt < 4; mt++) {
                    uint32_t w = (uint32_t)(a_mrow[mt] * 16 +
                                            (((cb + a_cadd) ^ a_msw[mt]) << 2));
                    uint32_t afr[4];
                    ldsm_x4(afr[0], afr[1], afr[2], afr[3], aslot + w * 4u);
                    if (CVT_A) {
                        afr[0] = frag_tf32(afr[0]);
                        afr[1] = frag_tf32(afr[1]);
                        afr[2] = frag_tf32(afr[2]);
                        afr[3] = frag_tf32(afr[3]);
                    }
#pragma unroll
                    for (int nt = 0; nt < 4; nt++)
                        mma_tf32(acc[mt][nt], afr, bfr[nt]);
                }
            }
        }
    };

    constexpr int KSTEP = 16 * PLANES;
    constexpr int PD    = NSLOT - 1;     // prefetch depth
    const int nstage = K / KSTEP;
#pragma unroll
    for (int s = 0; s < PD; s++) {
        if (s < nstage) issue_copy(s, s * KSTEP);
        cpa_commit();
    }
    cpa_wait<NSLOT - 2>();
    __syncthreads();

    for (int s = 0; s < nstage; s++) {
        if (s + PD < nstage) issue_copy((s + PD) % NSLOT, (s + PD) * KSTEP);
        cpa_commit();
        compute(s % NSLOT);
        cpa_wait<NSLOT - 2>();
        __syncthreads();
    }

    const int g = lane >> 2;
    const int c = lane & 3;
#pragma unroll
    for (int nt = 0; nt < 4; nt++) {
        const int cl  = wn + nt * 8 + c * 2;
        const float b0v = __ldg(biasp + cl);
        const float b1v = __ldg(biasp + cl + 1);
#pragma unroll
        for (int mt = 0; mt < 4; mt++) {
            const int r0 = row0 + wm + mt * 16 + g;
            if (r0 < M) {
                float2 o = make_float2(acc[mt][nt][0] + b0v, acc[mt][nt][1] + b1v);
                *(float2*)(C + (size_t)r0 * N + col0 + cl) = o;
            }
            if (r0 + 8 < M) {
                float2 o = make_float2(acc[mt][nt][2] + b0v, acc[mt][nt][3] + b1v);
                *(float2*)(C + (size_t)(r0 + 8) * N + col0 + cl) = o;
            }
        }
    }
}

// ---------------------------------------------------------------------------
// Sampling + in-warp softmax (R15 version): per-point geometry broadcast via
// shfl, branch-free clamped gathers, float2 lanes. Output ACC is stored
// tf32-rounded so the op-GEMM can skip its A-side cvt (bit-identical).
// ---------------------------------------------------------------------------
__global__ __launch_bounds__(256) void sample_kernel(
    const float* __restrict__ ref,    // [B, LQ, 4, 2]
    const float* __restrict__ v,      // [B, LV, H, HD]
    const float* __restrict__ soaw,   // [B*LQ, 384]
    float* __restrict__ acc_out)      // [B*LQ, 256]
{
    const int w    = blockIdx.x * 8 + (threadIdx.x >> 5);
    const int lane = threadIdx.x & 31;
    const int h    = w & 7;
    const int bq   = w >> 3;
    const int b    = bq >> 10;

    const int half = lane >> 4;
    const int ch   = (lane & 15) * 2;
    const int p    = lane & 15;

    const float*  row   = soaw + (size_t)bq * 384;
    const float2* so2   = (const float2*)(row + h * 32);
    const float*  aw_p  = row + 256 + h * 16;
    const float*  ref_p = ref + (size_t)bq * 8;
    const float*  vb    = v + (size_t)b * (cfg::LV * cfg::D) + h * 32 + ch;

    float logit = (lane < 16) ? aw_p[lane] : -1e30f;
    float mx = logit;
#pragma unroll
    for (int off = 8; off >= 1; off >>= 1)
        mx = fmaxf(mx, __shfl_xor_sync(0xffffffffu, mx, off));
    float e = __expf(logit - mx);
    float ssum = e;
#pragma unroll
    for (int off = 8; off >= 1; off >>= 1)
        ssum += __shfl_xor_sync(0xffffffffu, ssum, off);
    const float wnorm = e / ssum;

    const int lp = p >> 2;
    const int Wl = (lp == 0) ? 100 : (lp == 1) ? 50 : (lp == 2) ? 25 : 13;
    const float Wf = (float)Wl;

    const float2 so = so2[p];
    const float x = fmaf(ref_p[lp * 2 + 0], Wf, -0.5f) + so.x;
    const float y = fmaf(ref_p[lp * 2 + 1], Wf, -0.5f) + so.y;

    const float x0f = floorf(x), y0f = floorf(y);
    const int   ix0 = (int)x0f,  iy0 = (int)y0f;
    const float fx = x - x0f,    fy = y - y0f;

    const float wt = __shfl_sync(0xffffffffu, wnorm, p);

    const bool vx0 = (unsigned)ix0       < (unsigned)Wl;
    const bool vx1 = (unsigned)(ix0 + 1) < (unsigned)Wl;
    const bool vy0 = (unsigned)iy0       < (unsigned)Wl;
    const bool vy1 = (unsigned)(iy0 + 1) < (unsigned)Wl;

    const float gx0 = vx0 ? (1.f - fx) : 0.f;
    const float gx1 = vx1 ? fx         : 0.f;
    const float gy0 = vy0 ? wt * (1.f - fy) : 0.f;
    const float gy1 = vy1 ? wt * fy         : 0.f;

    const float my_w00 = gx0 * gy0, my_w01 = gx1 * gy0;
    const float my_w10 = gx0 * gy1, my_w11 = gx1 * gy1;

    const int cx0 = min(max(ix0, 0), Wl - 1);
    const int cx1 = min(max(ix0 + 1, 0), Wl - 1);
    const int cy0 = min(max(iy0, 0), Wl - 1);
    const int cy1 = min(max(iy0 + 1, 0), Wl - 1);
    const int rA = cy0 * Wl, rB = cy1 * Wl;
    const int my_o00 = (rA + cx0) * 256, my_o01 = (rA + cx1) * 256;
    const int my_o10 = (rB + cx0) * 256, my_o11 = (rB + cx1) * 256;

    const int LSTART[4] = {0, 10000, 12500, 13125};

    float2 acc2 = make_float2(0.f, 0.f);
#pragma unroll
    for (int l = 0; l < 4; l++) {
        const float* base = vb + (size_t)LSTART[l] * cfg::D;
#pragma unroll
        for (int pp = 0; pp < 2; pp++) {
            const int idx = l * 4 + pp * 2 + half;
            const int o00 = __shfl_sync(0xffffffffu, my_o00, idx);
            const int o01 = __shfl_sync(0xffffffffu, my_o01, idx);
            const int o10 = __shfl_sync(0xffffffffu, my_o10, idx);
            const int o11 = __shfl_sync(0xffffffffu, my_o11, idx);
            const float w00 = __shfl_sync(0xffffffffu, my_w00, idx);
            const float w01 = __shfl_sync(0xffffffffu, my_w01, idx);
            const float w10 = __shfl_sync(0xffffffffu, my_w10, idx);
            const float w11 = __shfl_sync(0xffffffffu, my_w11, idx);

            const float2 v00 = *(const float2*)(base + o00);
            const float2 v01 = *(const float2*)(base + o01);
            const float2 v10 = *(const float2*)(base + o10);
            const float2 v11 = *(const float2*)(base + o11);

            acc2.x += v00.x * w00 + v01.x * w01 + v10.x * w10 + v11.x * w11;
            acc2.y += v00.y * w00 + v01.y * w01 + v10.y * w10 + v11.y * w11;
        }
    }

    acc2.x += __shfl_xor_sync(0xffffffffu, acc2.x, 16);
    acc2.y += __shfl_xor_sync(0xffffffffu, acc2.y, 16);
    if (lane < 16) {
        // store tf32-rounded so op-GEMM skips A-side cvt (bit-identical)
        acc2.x = __uint_as_float(f2tf32(acc2.x));
        acc2.y = __uint_as_float(f2tf32(acc2.y));
        *(float2*)(acc_out + (size_t)bq * 256 + h * 32 + ch) = acc2;
    }
}

// ---------------------------------------------------------------------------
// Launch
// ---------------------------------------------------------------------------
extern "C" void kernel_launch(void* const* d_in, const int* in_sizes, int n_in,
                              void* d_out, int out_size)
{
    const float* query = (const float*)d_in[0];   // [8,1024,256]
    const float* refp  = (const float*)d_in[1];   // [8,1024,4,2]
    const float* value = (const float*)d_in[2];   // [8,13294,256]
    // d_in[3] = value_spatial_shapes (compile-time constant)
    const float* so_w  = (const float*)d_in[4];   // [256,256]  [K,N]
    const float* so_b  = (const float*)d_in[5];
    const float* aw_w  = (const float*)d_in[6];   // [256,128]  [K,N]
    const float* aw_b  = (const float*)d_in[7];
    const float* vp_w  = (const float*)d_in[8];   // [256,256]  [K,N]
    const float* vp_b  = (const float*)d_in[9];
    const float* op_w  = (const float*)d_in[10];  // [256,256]  [K,N]
    const float* op_b  = (const float*)d_in[11];
    float* out = (float*)d_out;                   // [8,1024,256]

    float* scratch = nullptr;
    cudaGetSymbolAddress((void**)&scratch, g_scratch);
    float* sV    = scratch + cfg::OFF_V;
    float* sSOAW = scratch + cfg::OFF_SOAW;
    float* sACC  = scratch + cfg::OFF_ACC;
    float* qR    = scratch + cfg::OFF_RND;
    float* soR   = qR  + 2097152;
    float* awR   = soR + 65536;
    float* opR   = awR + 32768;
    float* vpR   = opR + 65536;

    const int MQ = cfg::B * cfg::LQ;      // 8192
    const int MV = cfg::B * cfg::LV;      // 106352

    // 0) pre-round query + weights to tf32 (2272 blocks exactly)
    round_prep<<<2272, 256>>>((const float4*)query, (const float4*)so_w,
                              (const float4*)aw_w, (const float4*)op_w,
                              (const float4*)vp_w, (float4*)qR);
    // 1) v = value @ vp_w + vp_b   (BK16, 4-slot, A cvt in-loop)
    tf32_gemm_dual<true, 1, 4><<<dim3(2, (MV + 127) / 128), 256>>>(
        value, vpR, 256, vpR, 256, 256, vp_b, vp_b, sV, MV, 256, 256);
    // 2) soaw = queryR @ [so_wR | aw_wR] + bias   (BK32, 3-slot, cvt-free)
    tf32_gemm_dual<false, 2, 3><<<dim3(3, MQ / 128), 256>>>(
        qR, soR, 256, awR, 128, 256, so_b, aw_b, sSOAW, MQ, 384, 256);
    // 3) sampling (softmax folded in; stores rounded ACC)
    {
        int warps = cfg::B * cfg::LQ * cfg::H;   // 65536
        sample_kernel<<<warps / 8, 256>>>(refp, sV, sSOAW, sACC);
    }
    // 4) out = ACC @ op_wR + op_b   (BK32, 3-slot, cvt-free)
    tf32_gemm_dual<false, 2, 3><<<dim3(2, MQ / 128), 256>>>(
        sACC, opR, 256, opR, 256, 256, op_b, op_b, out, MQ, 256, 256);
}